// round 1
// baseline (speedup 1.0000x reference)
#include <cuda_runtime.h>
#include <math.h>

// Problem constants
#define N        10000
#define NPAIR    5000          // N/2, j points processed in packed pairs
#define DF       32
#define ITERS    4
#define JSPLIT   40            // j-range splits (parallelism over j)
#define JCHUNK   250           // j per split (even!)
#define PCHUNK   125           // packed pairs per split
#define ITILE    256           // i points per block (= threads)
#define NITILE   40            // ceil(N/ITILE)

// Scratch (static device allocation is allowed; cudaMalloc is not)
__device__ float g_pairs[NPAIR * 16];          // dual-layout j points, 320 KB
__device__ float g_part [JSPLIT * N * 12];     // partial ring sums, 19.2 MB
__device__ float g_h    [ITERS * N * DF];      // linear1 output, 5.1 MB
__device__ float g_stats[ITERS * DF * 2];      // (mu, inv_std) per feature
__device__ float g_w    [ITERS * N * 3];       // unnormalized softmax weights

// ---------------------------------------------------------------------------
// Logits pipeline (X_fea is constant -> compute all 4 iterations' weights once)
// ---------------------------------------------------------------------------
__global__ void linear1_kernel(const float* __restrict__ Xfea,
                               const float* __restrict__ W1,
                               const float* __restrict__ b1) {
    int it = blockIdx.y;
    int n  = blockIdx.x * blockDim.x + threadIdx.x;
    __shared__ float sW[DF * DF];
    __shared__ float sb[DF];
    for (int k = threadIdx.x; k < DF * DF; k += blockDim.x) sW[k] = W1[it * DF * DF + k];
    if (threadIdx.x < DF) sb[threadIdx.x] = b1[it * DF + threadIdx.x];
    __syncthreads();
    if (n >= N) return;

    float xf[DF];
    const float4* xr = (const float4*)(Xfea + n * DF);
    #pragma unroll
    for (int q = 0; q < DF / 4; q++) {
        float4 v = xr[q];
        xf[4*q] = v.x; xf[4*q+1] = v.y; xf[4*q+2] = v.z; xf[4*q+3] = v.w;
    }
    float* hout = g_h + (it * N + n) * DF;
    #pragma unroll 4
    for (int f = 0; f < DF; f++) {
        float acc = sb[f];
        #pragma unroll
        for (int k = 0; k < DF; k++) acc = fmaf(xf[k], sW[f * DF + k], acc);
        hout[f] = acc;
    }
}

__global__ void bnstats_kernel() {
    int it = blockIdx.x;
    int w  = threadIdx.x >> 5;   // 0..31 (warp id)
    int f  = threadIdx.x & 31;   // feature
    float s = 0.f, sq = 0.f;
    for (int n = w; n < N; n += 32) {
        float v = g_h[(it * N + n) * DF + f];
        s += v;
        sq = fmaf(v, v, sq);
    }
    __shared__ float ss[32 * 33];
    __shared__ float sqq[32 * 33];
    ss [w * 33 + f] = s;
    sqq[w * 33 + f] = sq;
    __syncthreads();
    if (threadIdx.x < DF) {
        float ts = 0.f, tq = 0.f;
        for (int ww = 0; ww < 32; ww++) { ts += ss[ww * 33 + f]; tq += sqq[ww * 33 + f]; }
        float mu  = ts / (float)N;
        float var = tq / (float)N - mu * mu;   // biased var, matches reference
        g_stats[(it * DF + f) * 2 + 0] = mu;
        g_stats[(it * DF + f) * 2 + 1] = rsqrtf(var + 1e-5f);
    }
}

__global__ void logits_kernel(const float* __restrict__ gamma,
                              const float* __restrict__ beta,
                              const float* __restrict__ W2,
                              const float* __restrict__ b2) {
    int it = blockIdx.y;
    int n  = blockIdx.x * blockDim.x + threadIdx.x;
    __shared__ float sg[DF], sbe[DF], smu[DF], sis[DF], sW2[3 * DF], sb2[3];
    if (threadIdx.x < DF) {
        sg [threadIdx.x] = gamma[it * DF + threadIdx.x];
        sbe[threadIdx.x] = beta [it * DF + threadIdx.x];
        smu[threadIdx.x] = g_stats[(it * DF + threadIdx.x) * 2 + 0];
        sis[threadIdx.x] = g_stats[(it * DF + threadIdx.x) * 2 + 1];
    }
    if (threadIdx.x < 3 * DF) sW2[threadIdx.x] = W2[it * 3 * DF + threadIdx.x];
    if (threadIdx.x < 3)      sb2[threadIdx.x] = b2[it * 3 + threadIdx.x];
    __syncthreads();
    if (n >= N) return;

    const float* hrow = g_h + (it * N + n) * DF;
    float a[DF];
    #pragma unroll
    for (int f = 0; f < DF; f++) {
        float v = (hrow[f] - smu[f]) * sis[f] * sg[f] + sbe[f];
        a[f] = fmaxf(v, 0.f);
    }
    float l0 = sb2[0], l1 = sb2[1], l2 = sb2[2];
    #pragma unroll
    for (int f = 0; f < DF; f++) {
        l0 = fmaf(a[f], sW2[0 * DF + f], l0);
        l1 = fmaf(a[f], sW2[1 * DF + f], l1);
        l2 = fmaf(a[f], sW2[2 * DF + f], l2);
    }
    // Store unnormalized exp(); finalize divides by the sum. Mathematically
    // identical to softmax followed by division by w.sum() (reference).
    float m = fmaxf(l0, fmaxf(l1, l2));
    float* wout = g_w + (it * N + n) * 3;
    wout[0] = expf(l0 - m);
    wout[1] = expf(l1 - m);
    wout[2] = expf(l2 - m);
}

// ---------------------------------------------------------------------------
// Mean-shift pair loop
// ---------------------------------------------------------------------------
// Dual layout per packed j-pair (16 floats):
//   A (dist path):  [x0 x1 y0 y1 z0 z1 nu0 nu1]   nu = -0.5*|xj|^2
//   B (accum path): [x0 y0 z0 1.0 x1 y1 z1 1.0]
__global__ void prep_kernel(const float* __restrict__ Xsrc) {
    int p = blockIdx.x * blockDim.x + threadIdx.x;
    if (p >= NPAIR) return;
    float x0 = Xsrc[(2*p    ) * 3 + 0], y0 = Xsrc[(2*p    ) * 3 + 1], z0 = Xsrc[(2*p    ) * 3 + 2];
    float x1 = Xsrc[(2*p + 1) * 3 + 0], y1 = Xsrc[(2*p + 1) * 3 + 1], z1 = Xsrc[(2*p + 1) * 3 + 2];
    float nu0 = -0.5f * (x0*x0 + y0*y0 + z0*z0);
    float nu1 = -0.5f * (x1*x1 + y1*y1 + z1*z1);
    float4* dst = (float4*)(g_pairs + p * 16);
    dst[0] = make_float4(x0, x1, y0, y1);
    dst[1] = make_float4(z0, z1, nu0, nu1);
    dst[2] = make_float4(x0, y0, z0, 1.0f);
    dst[3] = make_float4(x1, y1, z1, 1.0f);
}

__global__ void __launch_bounds__(ITILE) shift_kernel() {
    __shared__ __align__(16) float sj[JCHUNK * 8];   // 8 KB tile (125 packed pairs)

    int js  = blockIdx.y;
    int tid = threadIdx.x;

    // cooperative tile load (contiguous in g_pairs)
    const float4* src = (const float4*)(g_pairs + js * JCHUNK * 8);
    float4* d4 = (float4*)sj;
    for (int t = tid; t < JCHUNK * 2; t += ITILE) d4[t] = src[t];
    __syncthreads();

    int i  = blockIdx.x * ITILE + tid;
    int ii = (i < N) ? i : (N - 1);

    // own point from layout A
    int pb = (ii >> 1) * 16, h = ii & 1;
    float xi  = g_pairs[pb + 0 + h];
    float yi  = g_pairs[pb + 2 + h];
    float zi  = g_pairs[pb + 4 + h];
    float nui = g_pairs[pb + 6 + h];
    // d <= bw^2  <=>  (xi.xj - 0.5|xj|^2) >= 0.5|xi|^2 - 0.5 bw^2
    float th1 = -nui - 0.02f;    // bw=0.2
    float th2 = -nui - 1.445f;   // bw=1.7
    float th3 = -nui - 5.12f;    // bw=3.2

    unsigned long long xi2, yi2, zi2;
    asm("mov.b64 %0, {%1, %1};" : "=l"(xi2) : "f"(xi));
    asm("mov.b64 %0, {%1, %1};" : "=l"(yi2) : "f"(yi));
    asm("mov.b64 %0, {%1, %1};" : "=l"(zi2) : "f"(zi));

    // ring accumulators: (sumx,sumy) and (sumz,count) per bandwidth, packed f32x2
    unsigned long long a0 = 0ull, a1 = 0ull, a2 = 0ull, a3 = 0ull, a4 = 0ull, a5 = 0ull;

    const ulonglong2* tile = (const ulonglong2*)sj;
    #pragma unroll 5
    for (int p = 0; p < PCHUNK; p++) {
        ulonglong2 rA = tile[4 * p + 0];   // (x01, y01)
        ulonglong2 rB = tile[4 * p + 1];   // (z01, nu01)
        ulonglong2 rC = tile[4 * p + 2];   // (xy0, zc0)
        ulonglong2 rD = tile[4 * p + 3];   // (xy1, zc1)
        asm("{\n\t"
            ".reg .b64  t64;\n\t"
            ".reg .f32  vl, vh;\n\t"
            ".reg .pred pl1, pl2, pl3, ph1, ph2, ph3;\n\t"
            "fma.rn.f32x2 t64, %6, %9, %11;\n\t"     // xi*xj - 0.5|xj|^2 (seeded)
            "fma.rn.f32x2 t64, %7, %10, t64;\n\t"
            "fma.rn.f32x2 t64, %8, %12, t64;\n\t"
            "mov.b64 {vl, vh}, t64;\n\t"
            "setp.ge.f32 pl1, vl, %13;\n\t"
            "setp.ge.f32 pl2, vl, %14;\n\t"
            "setp.ge.f32 pl3, vl, %15;\n\t"
            "setp.ge.f32 ph1, vh, %13;\n\t"
            "setp.ge.f32 ph2, vh, %14;\n\t"
            "setp.ge.f32 ph3, vh, %15;\n\t"
            "@pl1 add.rn.f32x2 %0, %0, %16;\n\t"
            "@pl1 add.rn.f32x2 %1, %1, %17;\n\t"
            "@pl2 add.rn.f32x2 %2, %2, %16;\n\t"
            "@pl2 add.rn.f32x2 %3, %3, %17;\n\t"
            "@pl3 add.rn.f32x2 %4, %4, %16;\n\t"
            "@pl3 add.rn.f32x2 %5, %5, %17;\n\t"
            "@ph1 add.rn.f32x2 %0, %0, %18;\n\t"
            "@ph1 add.rn.f32x2 %1, %1, %19;\n\t"
            "@ph2 add.rn.f32x2 %2, %2, %18;\n\t"
            "@ph2 add.rn.f32x2 %3, %3, %19;\n\t"
            "@ph3 add.rn.f32x2 %4, %4, %18;\n\t"
            "@ph3 add.rn.f32x2 %5, %5, %19;\n\t"
            "}"
            : "+l"(a0), "+l"(a1), "+l"(a2), "+l"(a3), "+l"(a4), "+l"(a5)
            : "l"(xi2), "l"(yi2), "l"(zi2),
              "l"(rA.x), "l"(rA.y), "l"(rB.y), "l"(rB.x),
              "f"(th1), "f"(th2), "f"(th3),
              "l"(rC.x), "l"(rC.y), "l"(rD.x), "l"(rD.y));
    }

    if (i < N) {
        float4* dst = (float4*)(g_part + (js * N + i) * 12);
        dst[0] = make_float4(__uint_as_float((unsigned)a0), __uint_as_float((unsigned)(a0 >> 32)),
                             __uint_as_float((unsigned)a1), __uint_as_float((unsigned)(a1 >> 32)));
        dst[1] = make_float4(__uint_as_float((unsigned)a2), __uint_as_float((unsigned)(a2 >> 32)),
                             __uint_as_float((unsigned)a3), __uint_as_float((unsigned)(a3 >> 32)));
        dst[2] = make_float4(__uint_as_float((unsigned)a4), __uint_as_float((unsigned)(a4 >> 32)),
                             __uint_as_float((unsigned)a5), __uint_as_float((unsigned)(a5 >> 32)));
    }
}

__global__ void finalize_kernel(float* __restrict__ out, int it) {
    int i = blockIdx.x * blockDim.x + threadIdx.x;
    if (i >= N) return;
    float sx1=0,sy1=0,sz1=0,c1=0, sx2=0,sy2=0,sz2=0,c2=0, sx3=0,sy3=0,sz3=0,c3=0;
    for (int js = 0; js < JSPLIT; js++) {
        const float4* p = (const float4*)(g_part + (js * N + i) * 12);
        float4 v0 = p[0], v1 = p[1], v2 = p[2];
        sx1 += v0.x; sy1 += v0.y; sz1 += v0.z; c1 += v0.w;
        sx2 += v1.x; sy2 += v1.y; sz2 += v1.z; c2 += v1.w;
        sx3 += v2.x; sy3 += v2.y; sz3 += v2.z; c3 += v2.w;
    }
    const float* wp = g_w + (it * N + i) * 3;
    float e0 = wp[0], e1 = wp[1], e2 = wp[2];
    float inv = 1.0f / (e0 + e1 + e2);
    float r1 = e0 / c1, r2 = e1 / c2, r3 = e2 / c3;
    float nx = (sx1 * r1 + sx2 * r2 + sx3 * r3) * inv;
    float ny = (sy1 * r1 + sy2 * r2 + sy3 * r3) * inv;
    float nz = (sz1 * r1 + sz2 * r2 + sz3 * r3) * inv;
    float* o = out + (it * N + i) * 3;
    o[0] = nx; o[1] = ny; o[2] = nz;
}

// ---------------------------------------------------------------------------
// Inputs (metadata order = setup_inputs dict order):
//   0:X [N,3] 1:X_fea [N,32] 2:W1 [4,32,32] 3:b1 [4,32]
//   4:gamma [4,32] 5:beta [4,32] 6:W2 [4,3,32] 7:b2 [4,3]
// Output: [4, N, 3] float32
// ---------------------------------------------------------------------------
extern "C" void kernel_launch(void* const* d_in, const int* in_sizes, int n_in,
                              void* d_out, int out_size) {
    const float* X     = (const float*)d_in[0];
    const float* Xfea  = (const float*)d_in[1];
    const float* W1    = (const float*)d_in[2];
    const float* b1    = (const float*)d_in[3];
    const float* gamma = (const float*)d_in[4];
    const float* beta  = (const float*)d_in[5];
    const float* W2    = (const float*)d_in[6];
    const float* b2    = (const float*)d_in[7];
    float* out = (float*)d_out;

    linear1_kernel<<<dim3((N + 127) / 128, ITERS), 128>>>(Xfea, W1, b1);
    bnstats_kernel<<<ITERS, 1024>>>();
    logits_kernel<<<dim3((N + 255) / 256, ITERS), 256>>>(gamma, beta, W2, b2);

    for (int it = 0; it < ITERS; it++) {
        const float* Xsrc = (it == 0) ? X : (out + (it - 1) * N * 3);
        prep_kernel<<<(NPAIR + 127) / 128, 128>>>(Xsrc);
        shift_kernel<<<dim3(NITILE, JSPLIT), ITILE>>>();
        finalize_kernel<<<(N + 255) / 256, 256>>>(out, it);
    }
}

// round 2
// speedup vs baseline: 1.0485x; 1.0485x over previous
#include <cuda_runtime.h>
#include <math.h>

// Problem constants
#define N        10000
#define NPAIR    5000          // N/2 real packed j-pairs
#define DF       32
#define ITERS    4
#define JSPLIT   18            // j-range splits
#define JCHUNK   556           // j per split (even)
#define PCHUNK   278           // packed pairs per split
#define NPAIR_PAD (JSPLIT * PCHUNK)   // 5004 (4 sentinel pairs)
#define ITILE    256           // i points per block
#define NITILE   40            // ceil(N/ITILE)  -> grid 40*18=720 blocks, 1 wave @ occ>=5

// Scratch (static device arrays; cudaMalloc is forbidden)
__device__ float g_pairs[NPAIR_PAD * 16];      // dual-layout j points
__device__ float g_part [JSPLIT * N * 12];     // partial ring sums
__device__ float g_h    [ITERS * N * DF];      // linear1 output
__device__ float g_stats[ITERS * DF * 2];      // (mu, inv_std) per feature
__device__ float g_w    [ITERS * N * 3];       // unnormalized softmax weights

// ---------------------------------------------------------------------------
// Logits pipeline (X_fea constant -> all 4 iterations' weights computed once)
// ---------------------------------------------------------------------------
__global__ void linear1_kernel(const float* __restrict__ Xfea,
                               const float* __restrict__ W1,
                               const float* __restrict__ b1) {
    int it = blockIdx.y;
    int n  = blockIdx.x * blockDim.x + threadIdx.x;
    __shared__ float sW[DF * DF];
    __shared__ float sb[DF];
    for (int k = threadIdx.x; k < DF * DF; k += blockDim.x) sW[k] = W1[it * DF * DF + k];
    if (threadIdx.x < DF) sb[threadIdx.x] = b1[it * DF + threadIdx.x];
    __syncthreads();
    if (n >= N) return;

    float xf[DF];
    const float4* xr = (const float4*)(Xfea + n * DF);
    #pragma unroll
    for (int q = 0; q < DF / 4; q++) {
        float4 v = xr[q];
        xf[4*q] = v.x; xf[4*q+1] = v.y; xf[4*q+2] = v.z; xf[4*q+3] = v.w;
    }
    float* hout = g_h + (it * N + n) * DF;
    #pragma unroll 4
    for (int f = 0; f < DF; f++) {
        float acc = sb[f];
        #pragma unroll
        for (int k = 0; k < DF; k++) acc = fmaf(xf[k], sW[f * DF + k], acc);
        hout[f] = acc;
    }
}

__global__ void bnstats_kernel() {
    int it = blockIdx.x;
    int w  = threadIdx.x >> 5;
    int f  = threadIdx.x & 31;
    float s = 0.f, sq = 0.f;
    for (int n = w; n < N; n += 32) {
        float v = g_h[(it * N + n) * DF + f];
        s += v;
        sq = fmaf(v, v, sq);
    }
    __shared__ float ss[32 * 33];
    __shared__ float sqq[32 * 33];
    ss [w * 33 + f] = s;
    sqq[w * 33 + f] = sq;
    __syncthreads();
    if (threadIdx.x < DF) {
        float ts = 0.f, tq = 0.f;
        for (int ww = 0; ww < 32; ww++) { ts += ss[ww * 33 + f]; tq += sqq[ww * 33 + f]; }
        float mu  = ts / (float)N;
        float var = tq / (float)N - mu * mu;   // biased var (matches reference)
        g_stats[(it * DF + f) * 2 + 0] = mu;
        g_stats[(it * DF + f) * 2 + 1] = rsqrtf(var + 1e-5f);
    }
}

__global__ void logits_kernel(const float* __restrict__ gamma,
                              const float* __restrict__ beta,
                              const float* __restrict__ W2,
                              const float* __restrict__ b2) {
    int it = blockIdx.y;
    int n  = blockIdx.x * blockDim.x + threadIdx.x;
    __shared__ float sg[DF], sbe[DF], smu[DF], sis[DF], sW2[3 * DF], sb2[3];
    if (threadIdx.x < DF) {
        sg [threadIdx.x] = gamma[it * DF + threadIdx.x];
        sbe[threadIdx.x] = beta [it * DF + threadIdx.x];
        smu[threadIdx.x] = g_stats[(it * DF + threadIdx.x) * 2 + 0];
        sis[threadIdx.x] = g_stats[(it * DF + threadIdx.x) * 2 + 1];
    }
    if (threadIdx.x < 3 * DF) sW2[threadIdx.x] = W2[it * 3 * DF + threadIdx.x];
    if (threadIdx.x < 3)      sb2[threadIdx.x] = b2[it * 3 + threadIdx.x];
    __syncthreads();
    if (n >= N) return;

    const float* hrow = g_h + (it * N + n) * DF;
    float a[DF];
    #pragma unroll
    for (int f = 0; f < DF; f++) {
        float v = (hrow[f] - smu[f]) * sis[f] * sg[f] + sbe[f];
        a[f] = fmaxf(v, 0.f);
    }
    float l0 = sb2[0], l1 = sb2[1], l2 = sb2[2];
    #pragma unroll
    for (int f = 0; f < DF; f++) {
        l0 = fmaf(a[f], sW2[0 * DF + f], l0);
        l1 = fmaf(a[f], sW2[1 * DF + f], l1);
        l2 = fmaf(a[f], sW2[2 * DF + f], l2);
    }
    float m = fmaxf(l0, fmaxf(l1, l2));
    float* wout = g_w + (it * N + n) * 3;
    wout[0] = expf(l0 - m);
    wout[1] = expf(l1 - m);
    wout[2] = expf(l2 - m);
}

// ---------------------------------------------------------------------------
// Pair layout helpers
//   A (dist path):  [x0 x1 y0 y1 z0 z1 nu0 nu1]   nu = -0.5*|xj|^2
//   B (accum path): [x0 y0 z0 1.0 x1 y1 z1 1.0]
// ---------------------------------------------------------------------------
__device__ __forceinline__ void write_point_to_pairs(int i, float x, float y, float z) {
    int p = i >> 1, h = i & 1;
    float nu = -0.5f * (x * x + y * y + z * z);
    float* rec = g_pairs + p * 16;
    rec[0 + h] = x;
    rec[2 + h] = y;
    rec[4 + h] = z;
    rec[6 + h] = nu;
    *(float4*)(rec + 8 + 4 * h) = make_float4(x, y, z, 1.0f);
}

// Initial prep (it=0) + sentinel padding. Sentinels use coord 1e6 so the
// kernel test value v ~ -1.5e12 can never reach any threshold.
__global__ void prep0_kernel(const float* __restrict__ Xsrc) {
    int i = blockIdx.x * blockDim.x + threadIdx.x;
    if (i < N) {
        write_point_to_pairs(i, Xsrc[i * 3 + 0], Xsrc[i * 3 + 1], Xsrc[i * 3 + 2]);
    } else if (i < 2 * NPAIR_PAD) {
        write_point_to_pairs(i, 1e6f, 1e6f, 1e6f);
    }
}

// ---------------------------------------------------------------------------
// Mean-shift pair loop (single wave: 720 blocks, occ >= 5)
// ---------------------------------------------------------------------------
__global__ void __launch_bounds__(ITILE, 5) shift_kernel() {
    __shared__ __align__(16) float sj[JCHUNK * 8];   // 17.8 KB tile

    int js  = blockIdx.y;
    int tid = threadIdx.x;

    const float4* src = (const float4*)(g_pairs + js * JCHUNK * 8);
    float4* d4 = (float4*)sj;
    for (int t = tid; t < JCHUNK * 2; t += ITILE) d4[t] = src[t];
    __syncthreads();

    int i  = blockIdx.x * ITILE + tid;
    int ii = (i < N) ? i : (N - 1);

    int pb = (ii >> 1) * 16, h = ii & 1;
    float xi  = g_pairs[pb + 0 + h];
    float yi  = g_pairs[pb + 2 + h];
    float zi  = g_pairs[pb + 4 + h];
    float nui = g_pairs[pb + 6 + h];
    // d <= bw^2  <=>  (xi.xj - 0.5|xj|^2) >= 0.5|xi|^2 - 0.5 bw^2
    float th1 = -nui - 0.02f;    // bw=0.2
    float th2 = -nui - 1.445f;   // bw=1.7
    float th3 = -nui - 5.12f;    // bw=3.2

    unsigned long long xi2, yi2, zi2;
    asm("mov.b64 %0, {%1, %1};" : "=l"(xi2) : "f"(xi));
    asm("mov.b64 %0, {%1, %1};" : "=l"(yi2) : "f"(yi));
    asm("mov.b64 %0, {%1, %1};" : "=l"(zi2) : "f"(zi));

    // ring accumulators: (sumx,sumy) and (sumz,count) per bandwidth, packed f32x2
    unsigned long long a0 = 0ull, a1 = 0ull, a2 = 0ull, a3 = 0ull, a4 = 0ull, a5 = 0ull;

    const ulonglong2* tile = (const ulonglong2*)sj;
    #pragma unroll 2
    for (int p = 0; p < PCHUNK; p++) {
        ulonglong2 rA = tile[4 * p + 0];   // (x01, y01)
        ulonglong2 rB = tile[4 * p + 1];   // (z01, nu01)
        ulonglong2 rC = tile[4 * p + 2];   // (xy0, zc0)
        ulonglong2 rD = tile[4 * p + 3];   // (xy1, zc1)
        asm("{\n\t"
            ".reg .b64  t64;\n\t"
            ".reg .f32  vl, vh;\n\t"
            ".reg .pred pl1, pl2, pl3, ph1, ph2, ph3;\n\t"
            "fma.rn.f32x2 t64, %6, %9, %11;\n\t"     // xi*xj - 0.5|xj|^2 (seeded)
            "fma.rn.f32x2 t64, %7, %10, t64;\n\t"
            "fma.rn.f32x2 t64, %8, %12, t64;\n\t"
            "mov.b64 {vl, vh}, t64;\n\t"
            "setp.ge.f32 pl1, vl, %13;\n\t"
            "setp.ge.f32 pl2, vl, %14;\n\t"
            "setp.ge.f32 pl3, vl, %15;\n\t"
            "setp.ge.f32 ph1, vh, %13;\n\t"
            "setp.ge.f32 ph2, vh, %14;\n\t"
            "setp.ge.f32 ph3, vh, %15;\n\t"
            "@pl1 add.rn.f32x2 %0, %0, %16;\n\t"
            "@pl1 add.rn.f32x2 %1, %1, %17;\n\t"
            "@pl2 add.rn.f32x2 %2, %2, %16;\n\t"
            "@pl2 add.rn.f32x2 %3, %3, %17;\n\t"
            "@pl3 add.rn.f32x2 %4, %4, %16;\n\t"
            "@pl3 add.rn.f32x2 %5, %5, %17;\n\t"
            "@ph1 add.rn.f32x2 %0, %0, %18;\n\t"
            "@ph1 add.rn.f32x2 %1, %1, %19;\n\t"
            "@ph2 add.rn.f32x2 %2, %2, %18;\n\t"
            "@ph2 add.rn.f32x2 %3, %3, %19;\n\t"
            "@ph3 add.rn.f32x2 %4, %4, %18;\n\t"
            "@ph3 add.rn.f32x2 %5, %5, %19;\n\t"
            "}"
            : "+l"(a0), "+l"(a1), "+l"(a2), "+l"(a3), "+l"(a4), "+l"(a5)
            : "l"(xi2), "l"(yi2), "l"(zi2),
              "l"(rA.x), "l"(rA.y), "l"(rB.y), "l"(rB.x),
              "f"(th1), "f"(th2), "f"(th3),
              "l"(rC.x), "l"(rC.y), "l"(rD.x), "l"(rD.y));
    }

    if (i < N) {
        float4* dst = (float4*)(g_part + (js * N + i) * 12);
        dst[0] = make_float4(__uint_as_float((unsigned)a0), __uint_as_float((unsigned)(a0 >> 32)),
                             __uint_as_float((unsigned)a1), __uint_as_float((unsigned)(a1 >> 32)));
        dst[1] = make_float4(__uint_as_float((unsigned)a2), __uint_as_float((unsigned)(a2 >> 32)),
                             __uint_as_float((unsigned)a3), __uint_as_float((unsigned)(a3 >> 32)));
        dst[2] = make_float4(__uint_as_float((unsigned)a4), __uint_as_float((unsigned)(a4 >> 32)),
                             __uint_as_float((unsigned)a5), __uint_as_float((unsigned)(a5 >> 32)));
    }
}

// Finalize: reduce partials, apply mixture weights, write output point AND
// the pair layouts for the next iteration (prep fused in).
__global__ void finalize_kernel(float* __restrict__ out, int it) {
    int i = blockIdx.x * blockDim.x + threadIdx.x;
    if (i >= N) return;
    float sx1=0,sy1=0,sz1=0,c1=0, sx2=0,sy2=0,sz2=0,c2=0, sx3=0,sy3=0,sz3=0,c3=0;
    #pragma unroll 3
    for (int js = 0; js < JSPLIT; js++) {
        const float4* p = (const float4*)(g_part + (js * N + i) * 12);
        float4 v0 = p[0], v1 = p[1], v2 = p[2];
        sx1 += v0.x; sy1 += v0.y; sz1 += v0.z; c1 += v0.w;
        sx2 += v1.x; sy2 += v1.y; sz2 += v1.z; c2 += v1.w;
        sx3 += v2.x; sy3 += v2.y; sz3 += v2.z; c3 += v2.w;
    }
    const float* wp = g_w + (it * N + i) * 3;
    float e0 = wp[0], e1 = wp[1], e2 = wp[2];
    float inv = 1.0f / (e0 + e1 + e2);
    float r1 = e0 / c1, r2 = e1 / c2, r3 = e2 / c3;
    float nx = (sx1 * r1 + sx2 * r2 + sx3 * r3) * inv;
    float ny = (sy1 * r1 + sy2 * r2 + sy3 * r3) * inv;
    float nz = (sz1 * r1 + sz2 * r2 + sz3 * r3) * inv;
    float* o = out + (it * N + i) * 3;
    o[0] = nx; o[1] = ny; o[2] = nz;
    if (it < ITERS - 1) write_point_to_pairs(i, nx, ny, nz);
}

// ---------------------------------------------------------------------------
// Inputs: 0:X 1:X_fea 2:W1 3:b1 4:gamma 5:beta 6:W2 7:b2   Output: [4,N,3] f32
// ---------------------------------------------------------------------------
extern "C" void kernel_launch(void* const* d_in, const int* in_sizes, int n_in,
                              void* d_out, int out_size) {
    const float* X     = (const float*)d_in[0];
    const float* Xfea  = (const float*)d_in[1];
    const float* W1    = (const float*)d_in[2];
    const float* b1    = (const float*)d_in[3];
    const float* gamma = (const float*)d_in[4];
    const float* beta  = (const float*)d_in[5];
    const float* W2    = (const float*)d_in[6];
    const float* b2    = (const float*)d_in[7];
    float* out = (float*)d_out;

    linear1_kernel<<<dim3((N + 127) / 128, ITERS), 128>>>(Xfea, W1, b1);
    bnstats_kernel<<<ITERS, 1024>>>();
    logits_kernel<<<dim3((N + 255) / 256, ITERS), 256>>>(gamma, beta, W2, b2);

    prep0_kernel<<<(2 * NPAIR_PAD + 255) / 256, 256>>>(X);
    for (int it = 0; it < ITERS; it++) {
        shift_kernel<<<dim3(NITILE, JSPLIT), ITILE>>>();
        finalize_kernel<<<(N + 255) / 256, 256>>>(out, it);
    }
}

// round 3
// speedup vs baseline: 1.2925x; 1.2327x over previous
#include <cuda_runtime.h>
#include <math.h>

// Problem constants
#define N        10000
#define DF       32
#define ITERS    4
#define JSPLIT   14            // j-range splits
#define PCHUNK   358           // packed j-pairs per split (716 j)
#define NPAIR_PAD (JSPLIT * PCHUNK)   // 5012 pairs = 10024 j slots (24 sentinels)
#define ITILE    256           // i points per block
#define NITILE   40            // grid 40*14 = 560 blocks -> 1 wave @ occ 4
#define ZSCALE   16384.0f      // fixed-point scale for z accumulation (2^14)

// Scratch (static device arrays; cudaMalloc is forbidden)
__device__ float g_pairs[NPAIR_PAD * 16];      // dual-layout j points
__device__ float g_part [JSPLIT * N * 12];     // partial sums: 6 f32 + 3 s32(z) + 3 s32(cnt)
__device__ float g_h    [ITERS * N * DF];      // linear1 output
__device__ float g_stats[ITERS * DF * 2];      // (mu, inv_std)
__device__ float g_w    [ITERS * N * 3];       // unnormalized softmax weights

// ---------------------------------------------------------------------------
// Logits pipeline (X_fea constant -> all 4 iterations' weights computed once)
// ---------------------------------------------------------------------------
__global__ void linear1_kernel(const float* __restrict__ Xfea,
                               const float* __restrict__ W1,
                               const float* __restrict__ b1) {
    int it = blockIdx.y;
    int n  = blockIdx.x * blockDim.x + threadIdx.x;
    __shared__ float sW[DF * DF];
    __shared__ float sb[DF];
    for (int k = threadIdx.x; k < DF * DF; k += blockDim.x) sW[k] = W1[it * DF * DF + k];
    if (threadIdx.x < DF) sb[threadIdx.x] = b1[it * DF + threadIdx.x];
    __syncthreads();
    if (n >= N) return;

    float xf[DF];
    const float4* xr = (const float4*)(Xfea + n * DF);
    #pragma unroll
    for (int q = 0; q < DF / 4; q++) {
        float4 v = xr[q];
        xf[4*q] = v.x; xf[4*q+1] = v.y; xf[4*q+2] = v.z; xf[4*q+3] = v.w;
    }
    float* hout = g_h + (it * N + n) * DF;
    #pragma unroll 4
    for (int f = 0; f < DF; f++) {
        float acc = sb[f];
        #pragma unroll
        for (int k = 0; k < DF; k++) acc = fmaf(xf[k], sW[f * DF + k], acc);
        hout[f] = acc;
    }
}

__global__ void bnstats_kernel() {
    int it = blockIdx.x;
    int w  = threadIdx.x >> 5;
    int f  = threadIdx.x & 31;
    float s = 0.f, sq = 0.f;
    for (int n = w; n < N; n += 32) {
        float v = g_h[(it * N + n) * DF + f];
        s += v;
        sq = fmaf(v, v, sq);
    }
    __shared__ float ss[32 * 33];
    __shared__ float sqq[32 * 33];
    ss [w * 33 + f] = s;
    sqq[w * 33 + f] = sq;
    __syncthreads();
    if (threadIdx.x < DF) {
        float ts = 0.f, tq = 0.f;
        for (int ww = 0; ww < 32; ww++) { ts += ss[ww * 33 + f]; tq += sqq[ww * 33 + f]; }
        float mu  = ts / (float)N;
        float var = tq / (float)N - mu * mu;   // biased var (matches reference)
        g_stats[(it * DF + f) * 2 + 0] = mu;
        g_stats[(it * DF + f) * 2 + 1] = rsqrtf(var + 1e-5f);
    }
}

__global__ void logits_kernel(const float* __restrict__ gamma,
                              const float* __restrict__ beta,
                              const float* __restrict__ W2,
                              const float* __restrict__ b2) {
    int it = blockIdx.y;
    int n  = blockIdx.x * blockDim.x + threadIdx.x;
    __shared__ float sg[DF], sbe[DF], smu[DF], sis[DF], sW2[3 * DF], sb2[3];
    if (threadIdx.x < DF) {
        sg [threadIdx.x] = gamma[it * DF + threadIdx.x];
        sbe[threadIdx.x] = beta [it * DF + threadIdx.x];
        smu[threadIdx.x] = g_stats[(it * DF + threadIdx.x) * 2 + 0];
        sis[threadIdx.x] = g_stats[(it * DF + threadIdx.x) * 2 + 1];
    }
    if (threadIdx.x < 3 * DF) sW2[threadIdx.x] = W2[it * 3 * DF + threadIdx.x];
    if (threadIdx.x < 3)      sb2[threadIdx.x] = b2[it * 3 + threadIdx.x];
    __syncthreads();
    if (n >= N) return;

    const float* hrow = g_h + (it * N + n) * DF;
    float a[DF];
    #pragma unroll
    for (int f = 0; f < DF; f++) {
        float v = (hrow[f] - smu[f]) * sis[f] * sg[f] + sbe[f];
        a[f] = fmaxf(v, 0.f);
    }
    float l0 = sb2[0], l1 = sb2[1], l2 = sb2[2];
    #pragma unroll
    for (int f = 0; f < DF; f++) {
        l0 = fmaf(a[f], sW2[0 * DF + f], l0);
        l1 = fmaf(a[f], sW2[1 * DF + f], l1);
        l2 = fmaf(a[f], sW2[2 * DF + f], l2);
    }
    float m = fmaxf(l0, fmaxf(l1, l2));
    float* wout = g_w + (it * N + n) * 3;
    wout[0] = expf(l0 - m);
    wout[1] = expf(l1 - m);
    wout[2] = expf(l2 - m);
}

// ---------------------------------------------------------------------------
// Pair record (16 words per packed j-pair p):
//   [0..7]  dist path:  x0 x1 y0 y1 z0 z1 nu0 nu1      (nu = -0.5|x|^2)
//   [8..11] xy path:    x0 y0 x1 y1                     (packed f32x2 addends)
//   [12,13] z fixed:    round(z0*2^14), round(z1*2^14)  (s32)
//   [14,15] pad
// ---------------------------------------------------------------------------
__device__ __forceinline__ void write_point_to_pairs(int i, float x, float y, float z) {
    int p = i >> 1, h = i & 1;
    float nu = -0.5f * (x * x + y * y + z * z);
    float* rec = g_pairs + p * 16;
    rec[0 + h] = x;
    rec[2 + h] = y;
    rec[4 + h] = z;
    rec[6 + h] = nu;
    rec[8 + 2 * h] = x;
    rec[9 + 2 * h] = y;
    ((int*)rec)[12 + h] = __float2int_rn(z * ZSCALE);
}

// Initial prep + sentinel padding (coord 1e6 -> v ~ -1.5e12, never passes).
__global__ void prep0_kernel(const float* __restrict__ Xsrc) {
    int i = blockIdx.x * blockDim.x + threadIdx.x;
    if (i < N) {
        write_point_to_pairs(i, Xsrc[i * 3 + 0], Xsrc[i * 3 + 1], Xsrc[i * 3 + 2]);
    } else if (i < 2 * NPAIR_PAD) {
        write_point_to_pairs(i, 1e6f, 1e6f, 1e6f);
    }
}

// ---------------------------------------------------------------------------
// Mean-shift pair loop. fma pipe: 3 FFMA2 + 6 FADD2; alu pipe: 6 SETP + 12 IADD
// per packed j-pair -> balanced ~36 SMSP-cyc each.
// ---------------------------------------------------------------------------
__global__ void __launch_bounds__(ITILE, 4) shift_kernel() {
    __shared__ __align__(16) float sj[PCHUNK * 16];   // 22.9 KB tile

    int js  = blockIdx.y;
    int tid = threadIdx.x;

    const float4* src = (const float4*)(g_pairs + js * PCHUNK * 16);
    float4* d4 = (float4*)sj;
    for (int t = tid; t < PCHUNK * 4; t += ITILE) d4[t] = src[t];
    __syncthreads();

    int i  = blockIdx.x * ITILE + tid;
    int ii = (i < N) ? i : (N - 1);

    int pb = (ii >> 1) * 16, h = ii & 1;
    float xi  = g_pairs[pb + 0 + h];
    float yi  = g_pairs[pb + 2 + h];
    float zi  = g_pairs[pb + 4 + h];
    float nui = g_pairs[pb + 6 + h];
    // d <= bw^2  <=>  (xi.xj - 0.5|xj|^2) >= 0.5|xi|^2 - 0.5 bw^2
    float th1 = -nui - 0.02f;    // bw=0.2
    float th2 = -nui - 1.445f;   // bw=1.7
    float th3 = -nui - 5.12f;    // bw=3.2

    unsigned long long xi2, yi2, zi2;
    asm("mov.b64 %0, {%1, %1};" : "=l"(xi2) : "f"(xi));
    asm("mov.b64 %0, {%1, %1};" : "=l"(yi2) : "f"(yi));
    asm("mov.b64 %0, {%1, %1};" : "=l"(zi2) : "f"(zi));

    unsigned long long axy1 = 0ull, axy2 = 0ull, axy3 = 0ull;  // packed (sumx,sumy)
    int az1 = 0, az2 = 0, az3 = 0;                             // fixed-point z sums
    int ac1 = 0, ac2 = 0, ac3 = 0;                             // counts

    #pragma unroll 2
    for (int p = 0; p < PCHUNK; p++) {
        const float* rec = sj + p * 16;
        unsigned long long x01  = *(const unsigned long long*)(rec + 0);
        unsigned long long y01  = *(const unsigned long long*)(rec + 2);
        unsigned long long z01  = *(const unsigned long long*)(rec + 4);
        unsigned long long nu01 = *(const unsigned long long*)(rec + 6);
        unsigned long long xy0  = *(const unsigned long long*)(rec + 8);
        unsigned long long xy1  = *(const unsigned long long*)(rec + 10);
        int zf0 = ((const int*)rec)[12];
        int zf1 = ((const int*)rec)[13];
        asm("{\n\t"
            ".reg .b64  t64;\n\t"
            ".reg .f32  vl, vh;\n\t"
            ".reg .pred pl1, pl2, pl3, ph1, ph2, ph3;\n\t"
            "fma.rn.f32x2 t64, %9, %12, %15;\n\t"    // xi*xj - 0.5|xj|^2
            "fma.rn.f32x2 t64, %10, %13, t64;\n\t"
            "fma.rn.f32x2 t64, %11, %14, t64;\n\t"
            "mov.b64 {vl, vh}, t64;\n\t"
            "setp.ge.f32 pl1, vl, %16;\n\t"
            "setp.ge.f32 pl2, vl, %17;\n\t"
            "setp.ge.f32 pl3, vl, %18;\n\t"
            "setp.ge.f32 ph1, vh, %16;\n\t"
            "setp.ge.f32 ph2, vh, %17;\n\t"
            "setp.ge.f32 ph3, vh, %18;\n\t"
            "@pl1 add.rn.f32x2 %0, %0, %19;\n\t"
            "@pl1 add.s32 %3, %3, %21;\n\t"
            "@pl1 add.s32 %6, %6, 1;\n\t"
            "@pl2 add.rn.f32x2 %1, %1, %19;\n\t"
            "@pl2 add.s32 %4, %4, %21;\n\t"
            "@pl2 add.s32 %7, %7, 1;\n\t"
            "@pl3 add.rn.f32x2 %2, %2, %19;\n\t"
            "@pl3 add.s32 %5, %5, %21;\n\t"
            "@pl3 add.s32 %8, %8, 1;\n\t"
            "@ph1 add.rn.f32x2 %0, %0, %20;\n\t"
            "@ph1 add.s32 %3, %3, %22;\n\t"
            "@ph1 add.s32 %6, %6, 1;\n\t"
            "@ph2 add.rn.f32x2 %1, %1, %20;\n\t"
            "@ph2 add.s32 %4, %4, %22;\n\t"
            "@ph2 add.s32 %7, %7, 1;\n\t"
            "@ph3 add.rn.f32x2 %2, %2, %20;\n\t"
            "@ph3 add.s32 %5, %5, %22;\n\t"
            "@ph3 add.s32 %8, %8, 1;\n\t"
            "}"
            : "+l"(axy1), "+l"(axy2), "+l"(axy3),
              "+r"(az1), "+r"(az2), "+r"(az3),
              "+r"(ac1), "+r"(ac2), "+r"(ac3)
            : "l"(xi2), "l"(yi2), "l"(zi2),
              "l"(x01), "l"(y01), "l"(z01), "l"(nu01),
              "f"(th1), "f"(th2), "f"(th3),
              "l"(xy0), "l"(xy1), "r"(zf0), "r"(zf1));
    }

    if (i < N) {
        float* dst = g_part + (js * N + i) * 12;
        ((float4*)dst)[0] = make_float4(
            __uint_as_float((unsigned)axy1), __uint_as_float((unsigned)(axy1 >> 32)),
            __uint_as_float((unsigned)axy2), __uint_as_float((unsigned)(axy2 >> 32)));
        ((float4*)dst)[1] = make_float4(
            __uint_as_float((unsigned)axy3), __uint_as_float((unsigned)(axy3 >> 32)),
            __int_as_float(az1), __int_as_float(az2));
        ((float4*)dst)[2] = make_float4(
            __int_as_float(az3), __int_as_float(ac1),
            __int_as_float(ac2), __int_as_float(ac3));
    }
}

// Finalize: reduce partials, apply mixture weights, write output point AND
// next iteration's pair record (prep fused in).
__global__ void finalize_kernel(float* __restrict__ out, int it) {
    int i = blockIdx.x * blockDim.x + threadIdx.x;
    if (i >= N) return;
    float sx1=0,sy1=0,sx2=0,sy2=0,sx3=0,sy3=0;
    int   z1=0,z2=0,z3=0, c1=0,c2=0,c3=0;
    #pragma unroll 2
    for (int js = 0; js < JSPLIT; js++) {
        const float4* p = (const float4*)(g_part + (js * N + i) * 12);
        float4 v0 = p[0], v1 = p[1], v2 = p[2];
        sx1 += v0.x; sy1 += v0.y; sx2 += v0.z; sy2 += v0.w;
        sx3 += v1.x; sy3 += v1.y;
        z1 += __float_as_int(v1.z); z2 += __float_as_int(v1.w);
        z3 += __float_as_int(v2.x);
        c1 += __float_as_int(v2.y); c2 += __float_as_int(v2.z); c3 += __float_as_int(v2.w);
    }
    float sz1 = (float)z1 * (1.0f / ZSCALE);
    float sz2 = (float)z2 * (1.0f / ZSCALE);
    float sz3 = (float)z3 * (1.0f / ZSCALE);
    const float* wp = g_w + (it * N + i) * 3;
    float e0 = wp[0], e1 = wp[1], e2 = wp[2];
    float inv = 1.0f / (e0 + e1 + e2);
    float r1 = e0 / (float)c1, r2 = e1 / (float)c2, r3 = e2 / (float)c3;
    float nx = (sx1 * r1 + sx2 * r2 + sx3 * r3) * inv;
    float ny = (sy1 * r1 + sy2 * r2 + sy3 * r3) * inv;
    float nz = (sz1 * r1 + sz2 * r2 + sz3 * r3) * inv;
    float* o = out + (it * N + i) * 3;
    o[0] = nx; o[1] = ny; o[2] = nz;
    if (it < ITERS - 1) write_point_to_pairs(i, nx, ny, nz);
}

// ---------------------------------------------------------------------------
// Inputs: 0:X 1:X_fea 2:W1 3:b1 4:gamma 5:beta 6:W2 7:b2   Output: [4,N,3] f32
// Launch order puts shift_kernel at index 3 (where ncu captures).
// ---------------------------------------------------------------------------
extern "C" void kernel_launch(void* const* d_in, const int* in_sizes, int n_in,
                              void* d_out, int out_size) {
    const float* X     = (const float*)d_in[0];
    const float* Xfea  = (const float*)d_in[1];
    const float* W1    = (const float*)d_in[2];
    const float* b1    = (const float*)d_in[3];
    const float* gamma = (const float*)d_in[4];
    const float* beta  = (const float*)d_in[5];
    const float* W2    = (const float*)d_in[6];
    const float* b2    = (const float*)d_in[7];
    float* out = (float*)d_out;

    prep0_kernel<<<(2 * NPAIR_PAD + 255) / 256, 256>>>(X);            // 0
    linear1_kernel<<<dim3((N + 127) / 128, ITERS), 128>>>(Xfea, W1, b1); // 1
    bnstats_kernel<<<ITERS, 1024>>>();                                 // 2
    shift_kernel<<<dim3(NITILE, JSPLIT), ITILE>>>();                   // 3 <- ncu
    logits_kernel<<<dim3((N + 255) / 256, ITERS), 256>>>(gamma, beta, W2, b2); // 4
    finalize_kernel<<<(N + 255) / 256, 256>>>(out, 0);                 // 5
    for (int it = 1; it < ITERS; it++) {
        shift_kernel<<<dim3(NITILE, JSPLIT), ITILE>>>();
        finalize_kernel<<<(N + 255) / 256, 256>>>(out, it);
    }
}

// round 4
// speedup vs baseline: 1.3215x; 1.0225x over previous
#include <cuda_runtime.h>
#include <math.h>

// Problem constants
#define N        10000
#define DF       32
#define ITERS    4
#define JSPLIT   18            // j-range splits
#define PCHUNK   280           // packed j-pairs per split (560 j)
#define NPAIR_PAD (JSPLIT * PCHUNK)   // 5040 pairs = 10080 j slots (80 sentinels)
#define ITILE    256           // i points per block
#define NITILE   40            // grid 40*18 = 720 blocks -> 1 wave @ occ 5
#define ZSCALE   16384.0f      // fixed-point scale for z accumulation (2^14)

// Scratch (static device arrays; cudaMalloc is forbidden)
__device__ float g_pairs[NPAIR_PAD * 16];      // dual-layout j points
__device__ float g_part [JSPLIT * N * 12];     // partials: 6 f32 xy, 3 s32 z, 2 s32 cnt, 1 f32 cnt3
__device__ int   g_cnt  [ITERS * NITILE];      // stripe completion counters
__device__ float g_h    [ITERS * N * DF];      // linear1 output
__device__ float g_stats[ITERS * DF * 2];      // (mu, inv_std)
__device__ float g_w    [ITERS * N * 3];       // unnormalized softmax weights

// ---------------------------------------------------------------------------
// Logits pipeline (X_fea constant -> all 4 iterations' weights computed once)
// ---------------------------------------------------------------------------
__global__ void linear1_kernel(const float* __restrict__ Xfea,
                               const float* __restrict__ W1,
                               const float* __restrict__ b1) {
    int it = blockIdx.y;
    int n  = blockIdx.x * blockDim.x + threadIdx.x;
    __shared__ float sW[DF * DF];
    __shared__ float sb[DF];
    for (int k = threadIdx.x; k < DF * DF; k += blockDim.x) sW[k] = W1[it * DF * DF + k];
    if (threadIdx.x < DF) sb[threadIdx.x] = b1[it * DF + threadIdx.x];
    __syncthreads();
    if (n >= N) return;

    float xf[DF];
    const float4* xr = (const float4*)(Xfea + n * DF);
    #pragma unroll
    for (int q = 0; q < DF / 4; q++) {
        float4 v = xr[q];
        xf[4*q] = v.x; xf[4*q+1] = v.y; xf[4*q+2] = v.z; xf[4*q+3] = v.w;
    }
    float* hout = g_h + (it * N + n) * DF;
    #pragma unroll 4
    for (int f = 0; f < DF; f++) {
        float acc = sb[f];
        #pragma unroll
        for (int k = 0; k < DF; k++) acc = fmaf(xf[k], sW[f * DF + k], acc);
        hout[f] = acc;
    }
}

__global__ void bnstats_kernel() {
    int it = blockIdx.x;
    int w  = threadIdx.x >> 5;
    int f  = threadIdx.x & 31;
    float s = 0.f, sq = 0.f;
    for (int n = w; n < N; n += 32) {
        float v = g_h[(it * N + n) * DF + f];
        s += v;
        sq = fmaf(v, v, sq);
    }
    __shared__ float ss[32 * 33];
    __shared__ float sqq[32 * 33];
    ss [w * 33 + f] = s;
    sqq[w * 33 + f] = sq;
    __syncthreads();
    if (threadIdx.x < DF) {
        float ts = 0.f, tq = 0.f;
        for (int ww = 0; ww < 32; ww++) { ts += ss[ww * 33 + f]; tq += sqq[ww * 33 + f]; }
        float mu  = ts / (float)N;
        float var = tq / (float)N - mu * mu;   // biased var (matches reference)
        g_stats[(it * DF + f) * 2 + 0] = mu;
        g_stats[(it * DF + f) * 2 + 1] = rsqrtf(var + 1e-5f);
    }
}

__global__ void logits_kernel(const float* __restrict__ gamma,
                              const float* __restrict__ beta,
                              const float* __restrict__ W2,
                              const float* __restrict__ b2) {
    int it = blockIdx.y;
    int n  = blockIdx.x * blockDim.x + threadIdx.x;
    __shared__ float sg[DF], sbe[DF], smu[DF], sis[DF], sW2[3 * DF], sb2[3];
    if (threadIdx.x < DF) {
        sg [threadIdx.x] = gamma[it * DF + threadIdx.x];
        sbe[threadIdx.x] = beta [it * DF + threadIdx.x];
        smu[threadIdx.x] = g_stats[(it * DF + threadIdx.x) * 2 + 0];
        sis[threadIdx.x] = g_stats[(it * DF + threadIdx.x) * 2 + 1];
    }
    if (threadIdx.x < 3 * DF) sW2[threadIdx.x] = W2[it * 3 * DF + threadIdx.x];
    if (threadIdx.x < 3)      sb2[threadIdx.x] = b2[it * 3 + threadIdx.x];
    __syncthreads();
    if (n >= N) return;

    const float* hrow = g_h + (it * N + n) * DF;
    float a[DF];
    #pragma unroll
    for (int f = 0; f < DF; f++) {
        float v = (hrow[f] - smu[f]) * sis[f] * sg[f] + sbe[f];
        a[f] = fmaxf(v, 0.f);
    }
    float l0 = sb2[0], l1 = sb2[1], l2 = sb2[2];
    #pragma unroll
    for (int f = 0; f < DF; f++) {
        l0 = fmaf(a[f], sW2[0 * DF + f], l0);
        l1 = fmaf(a[f], sW2[1 * DF + f], l1);
        l2 = fmaf(a[f], sW2[2 * DF + f], l2);
    }
    float m = fmaxf(l0, fmaxf(l1, l2));
    float* wout = g_w + (it * N + n) * 3;
    wout[0] = expf(l0 - m);
    wout[1] = expf(l1 - m);
    wout[2] = expf(l2 - m);
}

// ---------------------------------------------------------------------------
// Pair record (16 words per packed j-pair p):
//   [0..7]  dist path:  x0 x1 y0 y1 z0 z1 nu0 nu1      (nu = -0.5|x|^2)
//   [8..11] xy path:    x0 y0 x1 y1                     (packed f32x2 addends)
//   [12,13] z fixed:    round(z0*2^14), round(z1*2^14)  (s32)
//   [14,15] pad
// ---------------------------------------------------------------------------
__device__ __forceinline__ void write_point_to_pairs(int i, float x, float y, float z) {
    int p = i >> 1, h = i & 1;
    float nu = -0.5f * (x * x + y * y + z * z);
    float* rec = g_pairs + p * 16;
    rec[0 + h] = x;
    rec[2 + h] = y;
    rec[4 + h] = z;
    rec[6 + h] = nu;
    rec[8 + 2 * h] = x;
    rec[9 + 2 * h] = y;
    ((int*)rec)[12 + h] = __float2int_rn(z * ZSCALE);
}

// Initial prep + sentinel padding + counter reset (each graph replay).
__global__ void prep0_kernel(const float* __restrict__ Xsrc) {
    int i = blockIdx.x * blockDim.x + threadIdx.x;
    if (i < ITERS * NITILE) g_cnt[i] = 0;
    if (i < N) {
        write_point_to_pairs(i, Xsrc[i * 3 + 0], Xsrc[i * 3 + 1], Xsrc[i * 3 + 2]);
    } else if (i < 2 * NPAIR_PAD) {
        write_point_to_pairs(i, 1e6f, 1e6f, 1e6f);
    }
}

// ---------------------------------------------------------------------------
// Mean-shift pair loop with embedded finalize (last block per i-stripe).
// Per packed pair: fma: 3 FFMA2 + 6 FADD2 + 2 FADD; alu: 6 FSETP + 10 IADD.
// ---------------------------------------------------------------------------
__global__ void __launch_bounds__(ITILE, 5) shift_kernel(float* __restrict__ out, int it) {
    __shared__ __align__(16) float sj[PCHUNK * 16];   // 17.9 KB tile

    int js  = blockIdx.y;
    int bx  = blockIdx.x;
    int tid = threadIdx.x;

    const float4* src = (const float4*)(g_pairs + js * PCHUNK * 16);
    float4* d4 = (float4*)sj;
    for (int t = tid; t < PCHUNK * 4; t += ITILE) d4[t] = src[t];
    __syncthreads();

    int i  = bx * ITILE + tid;
    int ii = (i < N) ? i : (N - 1);

    int pb = (ii >> 1) * 16, h = ii & 1;
    float xi  = g_pairs[pb + 0 + h];
    float yi  = g_pairs[pb + 2 + h];
    float zi  = g_pairs[pb + 4 + h];
    float nui = g_pairs[pb + 6 + h];
    // d <= bw^2  <=>  (xi.xj - 0.5|xj|^2) >= 0.5|xi|^2 - 0.5 bw^2
    float th1 = -nui - 0.02f;    // bw=0.2
    float th2 = -nui - 1.445f;   // bw=1.7
    float th3 = -nui - 5.12f;    // bw=3.2

    unsigned long long xi2, yi2, zi2;
    asm("mov.b64 %0, {%1, %1};" : "=l"(xi2) : "f"(xi));
    asm("mov.b64 %0, {%1, %1};" : "=l"(yi2) : "f"(yi));
    asm("mov.b64 %0, {%1, %1};" : "=l"(zi2) : "f"(zi));

    unsigned long long axy1 = 0ull, axy2 = 0ull, axy3 = 0ull;  // packed (sumx,sumy)
    int   az1 = 0, az2 = 0, az3 = 0;                           // fixed-point z sums
    int   ac1 = 0, ac2 = 0;                                    // counts bands 1,2
    float fc3 = 0.0f;                                          // count band 3 (fma pipe)

    #pragma unroll 2
    for (int p = 0; p < PCHUNK; p++) {
        const float* rec = sj + p * 16;
        unsigned long long x01  = *(const unsigned long long*)(rec + 0);
        unsigned long long y01  = *(const unsigned long long*)(rec + 2);
        unsigned long long z01  = *(const unsigned long long*)(rec + 4);
        unsigned long long nu01 = *(const unsigned long long*)(rec + 6);
        unsigned long long xy0  = *(const unsigned long long*)(rec + 8);
        unsigned long long xy1  = *(const unsigned long long*)(rec + 10);
        int zf0 = ((const int*)rec)[12];
        int zf1 = ((const int*)rec)[13];
        asm("{\n\t"
            ".reg .b64  t64;\n\t"
            ".reg .f32  vl, vh;\n\t"
            ".reg .pred pl1, pl2, pl3, ph1, ph2, ph3;\n\t"
            "fma.rn.f32x2 t64, %9, %12, %15;\n\t"    // xi*xj - 0.5|xj|^2
            "fma.rn.f32x2 t64, %10, %13, t64;\n\t"
            "fma.rn.f32x2 t64, %11, %14, t64;\n\t"
            "mov.b64 {vl, vh}, t64;\n\t"
            "setp.ge.f32 pl1, vl, %16;\n\t"
            "setp.ge.f32 pl2, vl, %17;\n\t"
            "setp.ge.f32 pl3, vl, %18;\n\t"
            "setp.ge.f32 ph1, vh, %16;\n\t"
            "setp.ge.f32 ph2, vh, %17;\n\t"
            "setp.ge.f32 ph3, vh, %18;\n\t"
            "@pl1 add.rn.f32x2 %0, %0, %19;\n\t"
            "@pl1 add.s32 %3, %3, %21;\n\t"
            "@pl1 add.s32 %6, %6, 1;\n\t"
            "@pl2 add.rn.f32x2 %1, %1, %19;\n\t"
            "@pl2 add.s32 %4, %4, %21;\n\t"
            "@pl2 add.s32 %7, %7, 1;\n\t"
            "@pl3 add.rn.f32x2 %2, %2, %19;\n\t"
            "@pl3 add.s32 %5, %5, %21;\n\t"
            "@pl3 add.f32 %8, %8, 0F3F800000;\n\t"
            "@ph1 add.rn.f32x2 %0, %0, %20;\n\t"
            "@ph1 add.s32 %3, %3, %22;\n\t"
            "@ph1 add.s32 %6, %6, 1;\n\t"
            "@ph2 add.rn.f32x2 %1, %1, %20;\n\t"
            "@ph2 add.s32 %4, %4, %22;\n\t"
            "@ph2 add.s32 %7, %7, 1;\n\t"
            "@ph3 add.rn.f32x2 %2, %2, %20;\n\t"
            "@ph3 add.s32 %5, %5, %22;\n\t"
            "@ph3 add.f32 %8, %8, 0F3F800000;\n\t"
            "}"
            : "+l"(axy1), "+l"(axy2), "+l"(axy3),
              "+r"(az1), "+r"(az2), "+r"(az3),
              "+r"(ac1), "+r"(ac2), "+f"(fc3)
            : "l"(xi2), "l"(yi2), "l"(zi2),
              "l"(x01), "l"(y01), "l"(z01), "l"(nu01),
              "f"(th1), "f"(th2), "f"(th3),
              "l"(xy0), "l"(xy1), "r"(zf0), "r"(zf1));
    }

    if (i < N) {
        float* dst = g_part + (js * N + i) * 12;
        ((float4*)dst)[0] = make_float4(
            __uint_as_float((unsigned)axy1), __uint_as_float((unsigned)(axy1 >> 32)),
            __uint_as_float((unsigned)axy2), __uint_as_float((unsigned)(axy2 >> 32)));
        ((float4*)dst)[1] = make_float4(
            __uint_as_float((unsigned)axy3), __uint_as_float((unsigned)(axy3 >> 32)),
            __int_as_float(az1), __int_as_float(az2));
        ((float4*)dst)[2] = make_float4(
            __int_as_float(az3), __int_as_float(ac1),
            __int_as_float(ac2), fc3);
    }
    __syncthreads();

    // last-block-done finalize for this i-stripe
    __shared__ int s_last;
    if (tid == 0) {
        __threadfence();
        int old = atomicAdd(&g_cnt[it * NITILE + bx], 1);
        s_last = (old == JSPLIT - 1) ? 1 : 0;
    }
    __syncthreads();
    if (!s_last) return;
    __threadfence();
    if (i >= N) return;

    float sx1=0,sy1=0,sx2=0,sy2=0,sx3=0,sy3=0, c3=0.f;
    int   z1=0,z2=0,z3=0, c1=0,c2=0;
    #pragma unroll 2
    for (int js2 = 0; js2 < JSPLIT; js2++) {
        const float4* p = (const float4*)(g_part + (js2 * N + i) * 12);
        float4 v0 = p[0], v1 = p[1], v2 = p[2];
        sx1 += v0.x; sy1 += v0.y; sx2 += v0.z; sy2 += v0.w;
        sx3 += v1.x; sy3 += v1.y;
        z1 += __float_as_int(v1.z); z2 += __float_as_int(v1.w);
        z3 += __float_as_int(v2.x);
        c1 += __float_as_int(v2.y); c2 += __float_as_int(v2.z); c3 += v2.w;
    }
    float sz1 = (float)z1 * (1.0f / ZSCALE);
    float sz2 = (float)z2 * (1.0f / ZSCALE);
    float sz3 = (float)z3 * (1.0f / ZSCALE);
    const float* wp = g_w + (it * N + i) * 3;
    float e0 = wp[0], e1 = wp[1], e2 = wp[2];
    float inv = 1.0f / (e0 + e1 + e2);
    float r1 = e0 / (float)c1, r2 = e1 / (float)c2, r3 = e2 / c3;
    float nx = (sx1 * r1 + sx2 * r2 + sx3 * r3) * inv;
    float ny = (sy1 * r1 + sy2 * r2 + sy3 * r3) * inv;
    float nz = (sz1 * r1 + sz2 * r2 + sz3 * r3) * inv;
    float* o = out + (it * N + i) * 3;
    o[0] = nx; o[1] = ny; o[2] = nz;
    if (it < ITERS - 1) write_point_to_pairs(i, nx, ny, nz);
}

// ---------------------------------------------------------------------------
// Inputs: 0:X 1:X_fea 2:W1 3:b1 4:gamma 5:beta 6:W2 7:b2   Output: [4,N,3] f32
// Launch order: ncu (-s 5) captures index 5 = shift_kernel(it=1).
// ---------------------------------------------------------------------------
extern "C" void kernel_launch(void* const* d_in, const int* in_sizes, int n_in,
                              void* d_out, int out_size) {
    const float* X     = (const float*)d_in[0];
    const float* Xfea  = (const float*)d_in[1];
    const float* W1    = (const float*)d_in[2];
    const float* b1    = (const float*)d_in[3];
    const float* gamma = (const float*)d_in[4];
    const float* beta  = (const float*)d_in[5];
    const float* W2    = (const float*)d_in[6];
    const float* b2    = (const float*)d_in[7];
    float* out = (float*)d_out;

    prep0_kernel<<<(2 * NPAIR_PAD + 255) / 256, 256>>>(X);                      // 0
    linear1_kernel<<<dim3((N + 127) / 128, ITERS), 128>>>(Xfea, W1, b1);        // 1
    bnstats_kernel<<<ITERS, 1024>>>();                                          // 2
    logits_kernel<<<dim3((N + 255) / 256, ITERS), 256>>>(gamma, beta, W2, b2);  // 3
    for (int it = 0; it < ITERS; it++)                                          // 4..7
        shift_kernel<<<dim3(NITILE, JSPLIT), ITILE>>>(out, it);
}